// round 1
// baseline (speedup 1.0000x reference)
#include <cuda_runtime.h>
#include <cuda_bf16.h>

#define IN_F   4096
#define OUT_F  11008
#define GRP    128
#define MROWS  32

#define COLS_PER_CTA   128     // 4 warps * 32 lanes, lane = column
#define THREADS        128
#define GROUPS_PER_CTA 4       // 512 K per CTA
#define KSPLIT         8       // 4096 / 512
#define CTAS_COL       (OUT_F / COLS_PER_CTA)   // 86
#define XS_STRIDE      36      // padded row stride (floats): 16B-aligned, low STS conflicts

// ---------------------------------------------------------------------------
// Init: out[s][o] = bf16_round(bias[o])   (output is poisoned before timing)
// ---------------------------------------------------------------------------
__global__ void init_out_kernel(const float* __restrict__ bias,
                                float* __restrict__ out)
{
    int o = blockIdx.x * blockDim.x + threadIdx.x;
    if (o < OUT_F) {
        float b = __bfloat162float(__float2bfloat16(bias[o]));
        #pragma unroll
        for (int s = 0; s < MROWS; s++)
            out[(size_t)s * OUT_F + o] = b;
    }
}

// ---------------------------------------------------------------------------
// Main: each CTA owns 128 output columns x 4 groups (512 K values).
// Lane = one output column; 32 fp32 row-accumulators packed as 16 f32x2.
// x chunk (128 k x 32 s) staged bf16-rounded + transposed in SMEM, read via
// broadcast LDS.128 (2 f32x2 row-pairs per load).
// ---------------------------------------------------------------------------
__global__ void __launch_bounds__(THREADS)
qlinear_pergrp_kernel(const float* __restrict__ x,
                      const int*   __restrict__ qweight,
                      const int*   __restrict__ qzeros,
                      const float* __restrict__ scales,
                      float*       __restrict__ out)
{
    __shared__ __align__(16) float xs[GRP * XS_STRIDE];

    const int bx    = blockIdx.x;
    const int ctile = bx % CTAS_COL;        // column tile
    const int kq    = bx / CTAS_COL;        // K split index 0..7
    const int tid   = threadIdx.x;
    const int warp  = tid >> 5;
    const int lane  = tid & 31;
    const int o     = ctile * COLS_PER_CTA + warp * 32 + lane;

    unsigned long long acc[16];
    #pragma unroll
    for (int j = 0; j < 16; j++) acc[j] = 0ULL;

    const int g0 = kq * GROUPS_PER_CTA;

    for (int gg = 0; gg < GROUPS_PER_CTA; gg++) {
        const int g     = g0 + gg;
        const int ibase = g * GRP;

        __syncthreads();   // previous group's xs reads done
        // ---- stage x[0:32][ibase:ibase+128] -> xs[i][s], bf16-rounded ----
        #pragma unroll
        for (int j = 0; j < 32; j++) {
            // idx = j*128 + tid  ->  s = j, i_local = tid (coalesced 512B rows)
            float v = x[(size_t)j * IN_F + ibase + tid];
            v = __bfloat162float(__float2bfloat16(v));
            xs[tid * XS_STRIDE + j] = v;
        }
        __syncthreads();

        // per-(group, column) dequant constants
        const float sc  = __bfloat162float(__float2bfloat16(scales[(size_t)g * OUT_F + o]));
        const float mqz = -(float)qzeros[(size_t)g * OUT_F + o] * sc;
        const int* wp   = qweight + (size_t)ibase * OUT_F + o;

        #pragma unroll 1
        for (int i = 0; i < GRP; i += 4) {
            // batch 4 weight loads for MLP
            int w0 = wp[0 * (size_t)OUT_F];
            int w1 = wp[1 * (size_t)OUT_F];
            int w2 = wp[2 * (size_t)OUT_F];
            int w3 = wp[3 * (size_t)OUT_F];
            wp += 4 * (size_t)OUT_F;

            #pragma unroll
            for (int u = 0; u < 4; u++) {
                int wv = (u == 0) ? w0 : (u == 1) ? w1 : (u == 2) ? w2 : w3;
                float wf = fmaf((float)wv, sc, mqz);   // (qw - qz) * sc
                unsigned long long wpack;
                asm("mov.b64 %0, {%1, %1};" : "=l"(wpack) : "f"(wf));

                const ulonglong2* xr =
                    (const ulonglong2*)(xs + (size_t)(i + u) * XS_STRIDE);
                #pragma unroll
                for (int q = 0; q < 8; q++) {
                    ulonglong2 xv = xr[q];   // LDS.128 broadcast: s pairs (4q..4q+3)
                    asm("fma.rn.f32x2 %0, %1, %2, %0;"
                        : "+l"(acc[2 * q])     : "l"(wpack), "l"(xv.x));
                    asm("fma.rn.f32x2 %0, %1, %2, %0;"
                        : "+l"(acc[2 * q + 1]) : "l"(wpack), "l"(xv.y));
                }
            }
        }
    }

    // ---- K-split reduction into bias-initialized output ----
    #pragma unroll
    for (int q = 0; q < 16; q++) {
        float lo, hi;
        asm("mov.b64 {%0, %1}, %2;" : "=f"(lo), "=f"(hi) : "l"(acc[q]));
        atomicAdd(&out[(size_t)(2 * q)     * OUT_F + o], lo);
        atomicAdd(&out[(size_t)(2 * q + 1) * OUT_F + o], hi);
    }
}

// ---------------------------------------------------------------------------
// Launch
// inputs (metadata order): x f32[1,32,4096], qweight i32[4096,11008],
//                          qzeros i32[32,11008], scales f32[32,11008],
//                          bias f32[11008]; output f32[1,32,11008]
// ---------------------------------------------------------------------------
extern "C" void kernel_launch(void* const* d_in, const int* in_sizes, int n_in,
                              void* d_out, int out_size)
{
    const float* x       = (const float*)d_in[0];
    const int*   qweight = (const int*)  d_in[1];
    const int*   qzeros  = (const int*)  d_in[2];
    const float* scales  = (const float*)d_in[3];
    const float* bias    = (const float*)d_in[4];
    float*       out     = (float*)d_out;

    init_out_kernel<<<(OUT_F + 255) / 256, 256>>>(bias, out);
    qlinear_pergrp_kernel<<<CTAS_COL * KSPLIT, THREADS>>>(x, qweight, qzeros, scales, out);
}